// round 14
// baseline (speedup 1.0000x reference)
#include <cuda_runtime.h>
#include <cuda_bf16.h>
#include <cstdint>

// Fixed shapes: N=16384 rows, C=2048 classes, D=512
#define N_ROWS 16384
#define N_CLS  2048
#define DIM    512
#define MARGIN 1.0f

// ---------------- device scratch (no runtime allocation) ----------------
__device__ __nv_bfloat16 g_WO_bf[N_ROWS * DIM];  // normalized WO, bf16
__device__ __nv_bfloat16 g_E_bf [N_CLS * DIM];   // emb, bf16
__device__ float    d_x2[N_ROWS];                // ||normalized row||^2 (fp32)
__device__ float    d_e2[N_CLS];                 // ||emb_c||^2 (fp32)
__device__ float    d_labelD2[N_ROWS];           // d^2 to true class
__device__ unsigned d_minBits[N_ROWS];           // min d^2 over other classes (float bits)
__device__ float    d_partial[64];               // partial loss sums
__device__ unsigned d_cnt = 0;                   // loss-reduce counter (wraps to 0)

// ---------------- helpers ----------------
__device__ __forceinline__ uint32_t smem_to_u32(const void* p) {
    uint32_t a;
    asm("{ .reg .u64 t; cvta.to.shared.u64 t, %1; cvt.u32.u64 %0, t; }" : "=r"(a) : "l"(p));
    return a;
}
#define CP_ASYNC_16(dst_u32, src_ptr) \
    asm volatile("cp.async.cg.shared.global [%0], [%1], 16;" :: "r"(dst_u32), "l"(src_ptr))
#define CP_ASYNC_COMMIT() asm volatile("cp.async.commit_group;" ::: "memory")
#define CP_ASYNC_WAIT1()  asm volatile("cp.async.wait_group 1;" ::: "memory")
#define CP_ASYNC_WAIT0()  asm volatile("cp.async.wait_group 0;" ::: "memory")
#define SW128(off) ((off) ^ (((off) >> 3) & 0x70))

__device__ __forceinline__ void ldsm_x4(uint32_t* r, uint32_t addr) {
    asm volatile("ldmatrix.sync.aligned.m8n8.x4.shared.b16 {%0,%1,%2,%3}, [%4];"
        : "=r"(r[0]), "=r"(r[1]), "=r"(r[2]), "=r"(r[3]) : "r"(addr));
}
__device__ __forceinline__ void mma_16816(float* c, const uint32_t* a, const uint32_t* b) {
    asm volatile(
        "mma.sync.aligned.m16n8k16.row.col.f32.bf16.bf16.f32 "
        "{%0,%1,%2,%3}, {%4,%5,%6,%7}, {%8,%9}, {%0,%1,%2,%3};"
        : "+f"(c[0]), "+f"(c[1]), "+f"(c[2]), "+f"(c[3])
        : "r"(a[0]), "r"(a[1]), "r"(a[2]), "r"(a[3]), "r"(b[0]), "r"(b[1]));
}

// ---------------- kernel 1: normalize WO -> bf16, x2, init minBits ----------------
__global__ void prep_wo(const float* __restrict__ WO) {
    int row = blockIdx.x * 8 + (threadIdx.x >> 5);
    int lane = threadIdx.x & 31;
    const float4* src = reinterpret_cast<const float4*>(WO + (size_t)row * DIM);
    float4 v[4];
    float s = 0.f;
    #pragma unroll
    for (int c = 0; c < 4; ++c) {
        v[c] = src[lane + 32 * c];
        s += v[c].x * v[c].x + v[c].y * v[c].y + v[c].z * v[c].z + v[c].w * v[c].w;
    }
    #pragma unroll
    for (int off = 16; off > 0; off >>= 1) s += __shfl_xor_sync(0xffffffffu, s, off);
    float inv = 1.f / fmaxf(sqrtf(s), 1e-12f);
    if (lane == 0) {
        d_x2[row] = (s * inv) * inv;
        d_minBits[row] = 0x7F800000u;  // +inf
    }
    uint2* dst = reinterpret_cast<uint2*>(g_WO_bf + (size_t)row * DIM);
    #pragma unroll
    for (int c = 0; c < 4; ++c) {
        __nv_bfloat162 p0 = __float22bfloat162_rn(make_float2(v[c].x * inv, v[c].y * inv));
        __nv_bfloat162 p1 = __float22bfloat162_rn(make_float2(v[c].z * inv, v[c].w * inv));
        uint2 u;
        u.x = *reinterpret_cast<uint32_t*>(&p0);
        u.y = *reinterpret_cast<uint32_t*>(&p1);
        dst[lane + 32 * c] = u;
    }
}

// ---------------- kernel 2: emb -> bf16, e2 ----------------
__global__ void prep_e(const float* __restrict__ E) {
    int row = blockIdx.x * 8 + (threadIdx.x >> 5);
    int lane = threadIdx.x & 31;
    const float4* src = reinterpret_cast<const float4*>(E + (size_t)row * DIM);
    float4 v[4];
    float s = 0.f;
    #pragma unroll
    for (int c = 0; c < 4; ++c) {
        v[c] = src[lane + 32 * c];
        s += v[c].x * v[c].x + v[c].y * v[c].y + v[c].z * v[c].z + v[c].w * v[c].w;
    }
    #pragma unroll
    for (int off = 16; off > 0; off >>= 1) s += __shfl_xor_sync(0xffffffffu, s, off);
    if (lane == 0) d_e2[row] = s;
    uint2* dst = reinterpret_cast<uint2*>(g_E_bf + (size_t)row * DIM);
    #pragma unroll
    for (int c = 0; c < 4; ++c) {
        __nv_bfloat162 p0 = __float22bfloat162_rn(make_float2(v[c].x, v[c].y));
        __nv_bfloat162 p1 = __float22bfloat162_rn(make_float2(v[c].z, v[c].w));
        uint2 u;
        u.x = *reinterpret_cast<uint32_t*>(&p0);
        u.y = *reinterpret_cast<uint32_t*>(&p1);
        dst[lane + 32 * c] = u;
    }
}

// ---------------- kernel 3: tiny init (positions gemm as 4th launch for ncu) ----
__global__ void init_misc() {
    if (threadIdx.x < 64) d_partial[threadIdx.x] = 0.f;
}

// ---------------- kernel 4: single-wave fused GEMM + register min/label epilogue -----
// Grid (2, 128) = 256 CTAs (one wave on 148 SMs, occ 2). Each CTA: rows [by*128,+128),
// cols [bx*1024,+1024) as 8 col-tiles of 128. One continuous 64-step 3-stage cp.async
// pipeline (fill paid once). Cross-tile min kept in registers; one reduction at end.
// 256 threads = 8 warps (2M x 4N), warp tile 64x32, 64 acc regs.
#define NTILES 8
#define NSTEP  (NTILES * 8)
#define STAGE_BYTES 32768         // A 16384 + B 16384
#define SMEM_B_IN_STAGE 16384
#define SMEM_E2_OFF (3 * STAGE_BYTES)            // 98304, 1024 floats = 4096 B
#define SMEM_RM_OFF (SMEM_E2_OFF + 4096)         // 102400, 128 x 4B
#define SMEM_GEMM_TOTAL (SMEM_RM_OFF + 512)      // 102912  (x2 = 201 KB < 227 KB)

__global__ __launch_bounds__(256, 2)
void gemm_mma(const int* __restrict__ label) {
    extern __shared__ char smem[];
    const uint32_t smem_u32 = smem_to_u32(smem);
    const int tid  = threadIdx.x;
    const int lane = tid & 31;
    const int wid  = tid >> 5;
    const int warpM = wid >> 2;          // 0..1 -> rows warpM*64
    const int warpN = wid & 3;           // 0..3 -> cols warpN*32
    const int rowBase  = blockIdx.y * 128;
    const int colStart = blockIdx.x * (NTILES * 128);

    float* e2s = reinterpret_cast<float*>(smem + SMEM_E2_OFF);
    unsigned* rowMinS = reinterpret_cast<unsigned*>(smem + SMEM_RM_OFF);
    if (tid < 128) rowMinS[tid] = 0x7F800000u;
    for (int i = tid; i < NTILES * 128; i += 256) e2s[i] = d_e2[colStart + i];

    // step loader: step g -> ct=g>>3 (col tile), kt=g&7 (k tile); slot g%3
    auto loadStep = [&](int g) {
        int ct = g >> 3, kt = g & 7;
        uint32_t sbase = smem_u32 + (g % 3) * STAGE_BYTES;
        const __nv_bfloat16* aBase = g_WO_bf + (size_t)rowBase * DIM + kt * 64;
        const __nv_bfloat16* bBase = g_E_bf + (size_t)(colStart + ct * 128) * DIM + kt * 64;
        #pragma unroll
        for (int i = 0; i < 4; ++i) {
            int q = tid + 256 * i;           // 0..1023
            int row = q >> 3, kc = q & 7;
            CP_ASYNC_16(sbase + SW128(row * 128 + kc * 16), aBase + (size_t)row * DIM + kc * 8);
            CP_ASYNC_16(sbase + SMEM_B_IN_STAGE + SW128(row * 128 + kc * 16),
                        bBase + (size_t)row * DIM + kc * 8);
        }
        CP_ASYNC_COMMIT();
    };

    float acc[4][4][4];
    #pragma unroll
    for (int mt = 0; mt < 4; ++mt)
        #pragma unroll
        for (int nt = 0; nt < 4; ++nt)
            #pragma unroll
            for (int e = 0; e < 4; ++e) acc[mt][nt][e] = 0.f;

    float mreg[4][2];                    // cross-tile min(d^2) per owned row slot
    #pragma unroll
    for (int mt = 0; mt < 4; ++mt) {
        mreg[mt][0] = __int_as_float(0x7f800000);
        mreg[mt][1] = __int_as_float(0x7f800000);
    }

    const int aRowOff = (warpM * 64 + (lane & 7) + ((lane >> 3) & 1) * 8) * 128 + (lane >> 4) * 16;
    const int bRowOff = (warpN * 32 + (lane & 7) + (lane >> 4) * 8) * 128 + ((lane >> 3) & 1) * 16;

    loadStep(0);
    loadStep(1);

    #pragma unroll 1
    for (int g = 0; g < NSTEP; ++g) {
        if (g < NSTEP - 2) CP_ASYNC_WAIT1();   // step g resident (g+1 may be in flight)
        else               CP_ASYNC_WAIT0();
        __syncthreads();                       // all reads of step g-1's slot done
        if (g + 2 < NSTEP) loadStep(g + 2);    // fills slot (g-1)%3 — safe

        const uint32_t sA = smem_u32 + (g % 3) * STAGE_BYTES;
        const uint32_t sB = sA + SMEM_B_IN_STAGE;
        #pragma unroll
        for (int ks = 0; ks < 4; ++ks) {
            uint32_t aF[4][4], bF[4][2];
            #pragma unroll
            for (int mt = 0; mt < 4; ++mt)
                ldsm_x4(aF[mt], sA + SW128(aRowOff + mt * 2048 + ks * 32));
            #pragma unroll
            for (int pr = 0; pr < 2; ++pr) {
                uint32_t t[4];
                ldsm_x4(t, sB + SW128(bRowOff + pr * 2048 + ks * 32));
                bF[2 * pr + 0][0] = t[0]; bF[2 * pr + 0][1] = t[1];
                bF[2 * pr + 1][0] = t[2]; bF[2 * pr + 1][1] = t[3];
            }
            #pragma unroll
            for (int mt = 0; mt < 4; ++mt)
                #pragma unroll
                for (int nt = 0; nt < 4; ++nt)
                    mma_16816(acc[mt][nt], aF[mt], bF[nt]);
        }

        if ((g & 7) == 7) {
            // per-col-tile epilogue, register-only: fold d2 into mreg, capture label
            int ct = g >> 3;
            int ctCol = colStart + ct * 128;
            #pragma unroll
            for (int mt = 0; mt < 4; ++mt) {
                #pragma unroll
                for (int half = 0; half < 2; ++half) {
                    int rl = warpM * 64 + mt * 16 + (lane >> 2) + half * 8;
                    int r  = rowBase + rl;
                    float x2v = __ldg(&d_x2[r]);
                    int   lab = __ldg(&label[r]);
                    float m = mreg[mt][half];
                    #pragma unroll
                    for (int nt = 0; nt < 4; ++nt) {
                        int c0 = ctCol + warpN * 32 + nt * 8 + 2 * (lane & 3);
                        float e20 = e2s[c0 - colStart];
                        float e21 = e2s[c0 - colStart + 1];
                        float d20 = fmaf(-2.f, acc[mt][nt][half * 2 + 0], x2v + e20);
                        float d21 = fmaf(-2.f, acc[mt][nt][half * 2 + 1], x2v + e21);
                        if (c0 == lab)     d_labelD2[r] = d20;
                        else               m = fminf(m, d20);
                        if (c0 + 1 == lab) d_labelD2[r] = d21;
                        else               m = fminf(m, d21);
                    }
                    mreg[mt][half] = m;
                }
            }
            #pragma unroll
            for (int mt = 0; mt < 4; ++mt)
                #pragma unroll
                for (int nt = 0; nt < 4; ++nt)
                    #pragma unroll
                    for (int e = 0; e < 4; ++e) acc[mt][nt][e] = 0.f;
        }
    }

    // final min reduction: shfl within 4-lane row group -> shared -> global
    #pragma unroll
    for (int mt = 0; mt < 4; ++mt) {
        #pragma unroll
        for (int half = 0; half < 2; ++half) {
            int rl = warpM * 64 + mt * 16 + (lane >> 2) + half * 8;
            float m = mreg[mt][half];
            m = fminf(m, __shfl_xor_sync(0xffffffffu, m, 1));
            m = fminf(m, __shfl_xor_sync(0xffffffffu, m, 2));
            if ((lane & 3) == 0) atomicMin(&rowMinS[rl], __float_as_uint(m));
        }
    }
    __syncthreads();
    if (tid < 128)
        atomicMin(&d_minBits[rowBase + tid], rowMinS[tid]);
}

// ---------------- kernel 5: loss reduction, single kernel (last block finishes) ------
__global__ void loss_reduce(float* __restrict__ out) {
    int tid = threadIdx.x;
    int n = blockIdx.x * 256 + tid;
    float ld = sqrtf(fmaxf(d_labelD2[n], 0.f));
    float md = sqrtf(fmaxf(__uint_as_float(d_minBits[n]), 0.f));
    float s = MARGIN + ld - md;
    #pragma unroll
    for (int off = 16; off > 0; off >>= 1) s += __shfl_xor_sync(0xffffffffu, s, off);
    __shared__ float sb[8];
    __shared__ unsigned lastFlag;
    if ((tid & 31) == 0) sb[tid >> 5] = s;
    __syncthreads();
    if (tid == 0) {
        float v = sb[0] + sb[1] + sb[2] + sb[3] + sb[4] + sb[5] + sb[6] + sb[7];
        d_partial[blockIdx.x] = v;
        __threadfence();
        unsigned prev = atomicInc(&d_cnt, 63);   // wraps to 0 after the 64th
        lastFlag = (prev == 63) ? 1u : 0u;
    }
    __syncthreads();
    if (lastFlag) {
        __threadfence();
        if (tid < 32) {
            float v = d_partial[tid] + d_partial[tid + 32];
            #pragma unroll
            for (int off = 16; off > 0; off >>= 1) v += __shfl_xor_sync(0xffffffffu, v, off);
            if (tid == 0) out[0] = v / (float)N_ROWS;
        }
    }
}

// ---------------- launch ----------------
extern "C" void kernel_launch(void* const* d_in, const int* in_sizes, int n_in,
                              void* d_out, int out_size) {
    const float* WO    = (const float*)d_in[0];
    const float* E     = (const float*)d_in[1];
    const int*   label = (const int*)d_in[2];
    float* out = (float*)d_out;

    cudaFuncSetAttribute(gemm_mma, cudaFuncAttributeMaxDynamicSharedMemorySize, SMEM_GEMM_TOTAL);

    prep_wo<<<N_ROWS / 8, 256>>>(WO);                 // launch 1
    prep_e<<<N_CLS / 8, 256>>>(E);                    // launch 2
    init_misc<<<1, 64>>>();                           // launch 3
    dim3 grid(2, 128);                                // 256 CTAs = one wave
    gemm_mma<<<grid, 256, SMEM_GEMM_TOTAL>>>(label);  // launch 4 <- ncu capture target
    loss_reduce<<<64, 256>>>(out);                    // launch 5
}

// round 15
// speedup vs baseline: 1.1308x; 1.1308x over previous
#include <cuda_runtime.h>
#include <cuda_fp16.h>
#include <cstdint>

// Fixed shapes: N=16384 rows, C=2048 classes, D=512
#define N_ROWS 16384
#define N_CLS  2048
#define DIM    512
#define MARGIN 1.0f

// ---------------- device scratch (no runtime allocation) ----------------
__device__ __half   g_WO_hf[N_ROWS * DIM];       // normalized WO, f16
__device__ __half   g_E_hf [N_CLS * DIM];        // emb, f16
__device__ float    d_x2[N_ROWS];                // ||normalized row||^2 (fp32)
__device__ float    d_e2[N_CLS];                 // ||emb_c||^2 (fp32)
__device__ float    d_labelD2[N_ROWS];           // d^2 to true class
__device__ unsigned d_minBits[N_ROWS];           // min d^2 over other classes (float bits)
__device__ float    d_partial[64];               // partial loss sums
__device__ unsigned d_cnt = 0;                   // loss-reduce counter (wraps to 0)

// ---------------- helpers ----------------
__device__ __forceinline__ uint32_t smem_to_u32(const void* p) {
    uint32_t a;
    asm("{ .reg .u64 t; cvta.to.shared.u64 t, %1; cvt.u32.u64 %0, t; }" : "=r"(a) : "l"(p));
    return a;
}
#define CP_ASYNC_16(dst_u32, src_ptr) \
    asm volatile("cp.async.cg.shared.global [%0], [%1], 16;" :: "r"(dst_u32), "l"(src_ptr))
#define CP_ASYNC_COMMIT() asm volatile("cp.async.commit_group;" ::: "memory")
#define CP_ASYNC_WAIT1()  asm volatile("cp.async.wait_group 1;" ::: "memory")
#define CP_ASYNC_WAIT0()  asm volatile("cp.async.wait_group 0;" ::: "memory")
#define SW128(off) ((off) ^ (((off) >> 3) & 0x70))

__device__ __forceinline__ void ldsm_x4(uint32_t* r, uint32_t addr) {
    asm volatile("ldmatrix.sync.aligned.m8n8.x4.shared.b16 {%0,%1,%2,%3}, [%4];"
        : "=r"(r[0]), "=r"(r[1]), "=r"(r[2]), "=r"(r[3]) : "r"(addr));
}
// f16 x f16 -> f16 accumulate (2 accum regs of f16x2)
__device__ __forceinline__ void mma_16816_f16(uint32_t* c, const uint32_t* a, const uint32_t* b) {
    asm volatile(
        "mma.sync.aligned.m16n8k16.row.col.f16.f16.f16.f16 "
        "{%0,%1}, {%2,%3,%4,%5}, {%6,%7}, {%0,%1};"
        : "+r"(c[0]), "+r"(c[1])
        : "r"(a[0]), "r"(a[1]), "r"(a[2]), "r"(a[3]), "r"(b[0]), "r"(b[1]));
}

// ---------------- kernel 1: normalize WO -> f16, x2, init minBits ----------------
__global__ void prep_wo(const float* __restrict__ WO) {
    int row = blockIdx.x * 8 + (threadIdx.x >> 5);
    int lane = threadIdx.x & 31;
    const float4* src = reinterpret_cast<const float4*>(WO + (size_t)row * DIM);
    float4 v[4];
    float s = 0.f;
    #pragma unroll
    for (int c = 0; c < 4; ++c) {
        v[c] = src[lane + 32 * c];
        s += v[c].x * v[c].x + v[c].y * v[c].y + v[c].z * v[c].z + v[c].w * v[c].w;
    }
    #pragma unroll
    for (int off = 16; off > 0; off >>= 1) s += __shfl_xor_sync(0xffffffffu, s, off);
    float inv = 1.f / fmaxf(sqrtf(s), 1e-12f);
    if (lane == 0) {
        d_x2[row] = (s * inv) * inv;
        d_minBits[row] = 0x7F800000u;  // +inf
    }
    uint2* dst = reinterpret_cast<uint2*>(g_WO_hf + (size_t)row * DIM);
    #pragma unroll
    for (int c = 0; c < 4; ++c) {
        __half2 p0 = __float22half2_rn(make_float2(v[c].x * inv, v[c].y * inv));
        __half2 p1 = __float22half2_rn(make_float2(v[c].z * inv, v[c].w * inv));
        uint2 u;
        u.x = *reinterpret_cast<uint32_t*>(&p0);
        u.y = *reinterpret_cast<uint32_t*>(&p1);
        dst[lane + 32 * c] = u;
    }
}

// ---------------- kernel 2: emb -> f16, e2 ----------------
__global__ void prep_e(const float* __restrict__ E) {
    int row = blockIdx.x * 8 + (threadIdx.x >> 5);
    int lane = threadIdx.x & 31;
    const float4* src = reinterpret_cast<const float4*>(E + (size_t)row * DIM);
    float4 v[4];
    float s = 0.f;
    #pragma unroll
    for (int c = 0; c < 4; ++c) {
        v[c] = src[lane + 32 * c];
        s += v[c].x * v[c].x + v[c].y * v[c].y + v[c].z * v[c].z + v[c].w * v[c].w;
    }
    #pragma unroll
    for (int off = 16; off > 0; off >>= 1) s += __shfl_xor_sync(0xffffffffu, s, off);
    if (lane == 0) d_e2[row] = s;
    uint2* dst = reinterpret_cast<uint2*>(g_E_hf + (size_t)row * DIM);
    #pragma unroll
    for (int c = 0; c < 4; ++c) {
        __half2 p0 = __float22half2_rn(make_float2(v[c].x, v[c].y));
        __half2 p1 = __float22half2_rn(make_float2(v[c].z, v[c].w));
        uint2 u;
        u.x = *reinterpret_cast<uint32_t*>(&p0);
        u.y = *reinterpret_cast<uint32_t*>(&p1);
        dst[lane + 32 * c] = u;
    }
}

// ---------------- kernel 3: tiny init (positions gemm as 4th launch for ncu) ----
__global__ void init_misc() {
    if (threadIdx.x < 64) d_partial[threadIdx.x] = 0.f;
}

// ---------------- kernel 4: fused mma.sync GEMM (f16 accum) + d2/min/label epilogue --
// Grid (16, 128). 256 threads = 8 warps (2M x 4N), warp tile 64x32.
// CTA tile 128x128, BK=64, 3-stage cp.async pipeline (ONE __syncthreads per k-iter),
// SW128 swizzle, occupancy 2. Accumulators: f16x2 (2 regs per m16n8 tile).
#define STAGE_BYTES 32768         // A 16384 + B 16384
#define SMEM_B_IN_STAGE 16384
#define SMEM_RM_OFF (3 * STAGE_BYTES)          // 98304, 128 x 4B
#define SMEM_GEMM_TOTAL (SMEM_RM_OFF + 512)    // 98816

__global__ __launch_bounds__(256, 2)
void gemm_mma(const int* __restrict__ label) {
    extern __shared__ char smem[];
    const uint32_t smem_u32 = smem_to_u32(smem);
    const int tid  = threadIdx.x;
    const int lane = tid & 31;
    const int wid  = tid >> 5;
    const int warpM = wid >> 2;          // 0..1 -> rows warpM*64
    const int warpN = wid & 3;           // 0..3 -> cols warpN*32
    const int rowBase = blockIdx.y * 128;
    const int colBase = blockIdx.x * 128;

    unsigned* rowMinS = reinterpret_cast<unsigned*>(smem + SMEM_RM_OFF);
    if (tid < 128) rowMinS[tid] = 0x7F800000u;

    // stage loader: A 128x64 f16 (1024 16B chunks) + B 128x64 (1024), 4+4/thread
    auto loadTile = [&](int kt, int s) {
        uint32_t sbase = smem_u32 + s * STAGE_BYTES;
        #pragma unroll
        for (int i = 0; i < 4; ++i) {
            int q = tid + 256 * i;           // 0..1023
            int row = q >> 3, kc = q & 7;
            const void* srcA = g_WO_hf + (size_t)(rowBase + row) * DIM + kt * 64 + kc * 8;
            CP_ASYNC_16(sbase + SW128(row * 128 + kc * 16), srcA);
            const void* srcB = g_E_hf + (size_t)(colBase + row) * DIM + kt * 64 + kc * 8;
            CP_ASYNC_16(sbase + SMEM_B_IN_STAGE + SW128(row * 128 + kc * 16), srcB);
        }
        CP_ASYNC_COMMIT();
    };

    uint32_t acc[4][4][2];               // f16x2 accumulators
    #pragma unroll
    for (int mt = 0; mt < 4; ++mt)
        #pragma unroll
        for (int nt = 0; nt < 4; ++nt) { acc[mt][nt][0] = 0u; acc[mt][nt][1] = 0u; }

    const int aRowOff = (warpM * 64 + (lane & 7) + ((lane >> 3) & 1) * 8) * 128 + (lane >> 4) * 16;
    const int bRowOff = (warpN * 32 + (lane & 7) + (lane >> 4) * 8) * 128 + ((lane >> 3) & 1) * 16;

    loadTile(0, 0);
    loadTile(1, 1);

    #pragma unroll 1
    for (int kt = 0; kt < 8; ++kt) {
        if (kt < 6) CP_ASYNC_WAIT1();   // stage kt resident (kt+1 may be in flight)
        else        CP_ASYNC_WAIT0();
        __syncthreads();                // all reads of stage kt-1 done
        if (kt + 2 < 8) loadTile(kt + 2, (kt + 2) % 3);  // fills slot (kt-1)%3 — safe

        const uint32_t sA = smem_u32 + (kt % 3) * STAGE_BYTES;
        const uint32_t sB = sA + SMEM_B_IN_STAGE;
        #pragma unroll
        for (int ks = 0; ks < 4; ++ks) {
            uint32_t aF[4][4], bF[4][2];
            #pragma unroll
            for (int mt = 0; mt < 4; ++mt)
                ldsm_x4(aF[mt], sA + SW128(aRowOff + mt * 2048 + ks * 32));
            #pragma unroll
            for (int pr = 0; pr < 2; ++pr) {
                uint32_t t[4];
                ldsm_x4(t, sB + SW128(bRowOff + pr * 2048 + ks * 32));
                bF[2 * pr + 0][0] = t[0]; bF[2 * pr + 0][1] = t[1];
                bF[2 * pr + 1][0] = t[2]; bF[2 * pr + 1][1] = t[3];
            }
            #pragma unroll
            for (int mt = 0; mt < 4; ++mt)
                #pragma unroll
                for (int nt = 0; nt < 4; ++nt)
                    mma_16816_f16(acc[mt][nt], aF[mt], bF[nt]);
        }
    }

    // epilogue in d^2 space: d2 = x2 + e2 - 2*dot; exclude label col from min
    // f16 C-frag layout: reg h (0/1) holds rows (lane>>2)+8h, packed cols {c0, c0+1}
    #pragma unroll
    for (int mt = 0; mt < 4; ++mt) {
        #pragma unroll
        for (int half = 0; half < 2; ++half) {
            int rl = warpM * 64 + mt * 16 + (lane >> 2) + half * 8;
            int r  = rowBase + rl;
            float x2v = __ldg(&d_x2[r]);
            int   lab = __ldg(&label[r]);
            float m = __int_as_float(0x7f800000);
            #pragma unroll
            for (int nt = 0; nt < 4; ++nt) {
                int c0 = colBase + warpN * 32 + nt * 8 + 2 * (lane & 3);
                __half2 hp = *reinterpret_cast<__half2*>(&acc[mt][nt][half]);
                float2 f = __half22float2(hp);
                float d20 = fmaf(-2.f, f.x, x2v + __ldg(&d_e2[c0]));
                float d21 = fmaf(-2.f, f.y, x2v + __ldg(&d_e2[c0 + 1]));
                if (c0 == lab)     d_labelD2[r] = d20;
                else               m = fminf(m, d20);
                if (c0 + 1 == lab) d_labelD2[r] = d21;
                else               m = fminf(m, d21);
            }
            m = fminf(m, __shfl_xor_sync(0xffffffffu, m, 1));
            m = fminf(m, __shfl_xor_sync(0xffffffffu, m, 2));
            if ((lane & 3) == 0) atomicMin(&rowMinS[rl], __float_as_uint(m));
        }
    }
    __syncthreads();
    if (tid < 128)
        atomicMin(&d_minBits[rowBase + tid], rowMinS[tid]);
}

// ---------------- kernel 5: loss reduction, single kernel (last block finishes) ------
__global__ void loss_reduce(float* __restrict__ out) {
    int tid = threadIdx.x;
    int n = blockIdx.x * 256 + tid;
    float ld = sqrtf(fmaxf(d_labelD2[n], 0.f));
    float md = sqrtf(fmaxf(__uint_as_float(d_minBits[n]), 0.f));
    float s = MARGIN + ld - md;
    #pragma unroll
    for (int off = 16; off > 0; off >>= 1) s += __shfl_xor_sync(0xffffffffu, s, off);
    __shared__ float sb[8];
    __shared__ unsigned lastFlag;
    if ((tid & 31) == 0) sb[tid >> 5] = s;
    __syncthreads();
    if (tid == 0) {
        float v = sb[0] + sb[1] + sb[2] + sb[3] + sb[4] + sb[5] + sb[6] + sb[7];
        d_partial[blockIdx.x] = v;
        __threadfence();
        unsigned prev = atomicInc(&d_cnt, 63);   // wraps to 0 after the 64th
        lastFlag = (prev == 63) ? 1u : 0u;
    }
    __syncthreads();
    if (lastFlag) {
        __threadfence();
        if (tid < 32) {
            float v = d_partial[tid] + d_partial[tid + 32];
            #pragma unroll
            for (int off = 16; off > 0; off >>= 1) v += __shfl_xor_sync(0xffffffffu, v, off);
            if (tid == 0) out[0] = v / (float)N_ROWS;
        }
    }
}

// ---------------- launch ----------------
extern "C" void kernel_launch(void* const* d_in, const int* in_sizes, int n_in,
                              void* d_out, int out_size) {
    const float* WO    = (const float*)d_in[0];
    const float* E     = (const float*)d_in[1];
    const int*   label = (const int*)d_in[2];
    float* out = (float*)d_out;

    cudaFuncSetAttribute(gemm_mma, cudaFuncAttributeMaxDynamicSharedMemorySize, SMEM_GEMM_TOTAL);

    prep_wo<<<N_ROWS / 8, 256>>>(WO);                 // launch 1
    prep_e<<<N_CLS / 8, 256>>>(E);                    // launch 2
    init_misc<<<1, 64>>>();                           // launch 3
    dim3 grid(N_CLS / 128, N_ROWS / 128);             // (16, 128)
    gemm_mma<<<grid, 256, SMEM_GEMM_TOTAL>>>(label);  // launch 4 <- ncu capture target
    loss_reduce<<<64, 256>>>(out);                    // launch 5
}

// round 16
// speedup vs baseline: 1.2060x; 1.0664x over previous
#include <cuda_runtime.h>
#include <cuda_bf16.h>
#include <cstdint>

// Fixed shapes: N=16384 rows, C=2048 classes, D=512
#define N_ROWS 16384
#define N_CLS  2048
#define DIM    512
#define MARGIN 1.0f

// ---------------- device scratch (no runtime allocation) ----------------
__device__ __nv_bfloat16 g_WO_bf[N_ROWS * DIM];  // normalized WO, bf16
__device__ __nv_bfloat16 g_E_bf [N_CLS * DIM];   // emb, bf16
__device__ float    d_x2[N_ROWS];                // ||normalized row||^2 (fp32)
__device__ float    d_e2[N_CLS];                 // ||emb_c||^2 (fp32)
__device__ float    d_labelD2[N_ROWS];           // d^2 to true class
__device__ unsigned d_minBits[N_ROWS];           // min d^2 over other classes (float bits)
__device__ float    d_partial[64];               // partial loss sums (fully written each run)
__device__ unsigned d_cnt = 0;                   // loss-reduce counter (atomicInc wraps -> reusable)

// ---------------- helpers ----------------
__device__ __forceinline__ uint32_t smem_to_u32(const void* p) {
    uint32_t a;
    asm("{ .reg .u64 t; cvta.to.shared.u64 t, %1; cvt.u32.u64 %0, t; }" : "=r"(a) : "l"(p));
    return a;
}
#define CP_ASYNC_16(dst_u32, src_ptr) \
    asm volatile("cp.async.cg.shared.global [%0], [%1], 16;" :: "r"(dst_u32), "l"(src_ptr))
#define CP_ASYNC_COMMIT() asm volatile("cp.async.commit_group;" ::: "memory")
#define CP_ASYNC_WAIT1()  asm volatile("cp.async.wait_group 1;" ::: "memory")
#define CP_ASYNC_WAIT0()  asm volatile("cp.async.wait_group 0;" ::: "memory")
#define SW128(off) ((off) ^ (((off) >> 3) & 0x70))

__device__ __forceinline__ void ldsm_x4(uint32_t* r, uint32_t addr) {
    asm volatile("ldmatrix.sync.aligned.m8n8.x4.shared.b16 {%0,%1,%2,%3}, [%4];"
        : "=r"(r[0]), "=r"(r[1]), "=r"(r[2]), "=r"(r[3]) : "r"(addr));
}
__device__ __forceinline__ void mma_16816(float* c, const uint32_t* a, const uint32_t* b) {
    asm volatile(
        "mma.sync.aligned.m16n8k16.row.col.f32.bf16.bf16.f32 "
        "{%0,%1,%2,%3}, {%4,%5,%6,%7}, {%8,%9}, {%0,%1,%2,%3};"
        : "+f"(c[0]), "+f"(c[1]), "+f"(c[2]), "+f"(c[3])
        : "r"(a[0]), "r"(a[1]), "r"(a[2]), "r"(a[3]), "r"(b[0]), "r"(b[1]));
}

// ---------------- kernel 1: combined prep (WO-normalize + E convert) --------------
// Blocks [0, N_ROWS/8): WO rows (normalize -> bf16, x2, init minBits)
// Blocks [N_ROWS/8, N_ROWS/8 + N_CLS/8): E rows (convert -> bf16, e2)
__global__ void prep_all(const float* __restrict__ WO, const float* __restrict__ E) {
    int blk = blockIdx.x;
    int lane = threadIdx.x & 31;
    bool isWO = blk < (N_ROWS / 8);
    int row = (isWO ? blk : blk - N_ROWS / 8) * 8 + (threadIdx.x >> 5);

    const float* srcBase = isWO ? WO : E;
    const float4* src = reinterpret_cast<const float4*>(srcBase + (size_t)row * DIM);
    float4 v[4];
    float s = 0.f;
    #pragma unroll
    for (int c = 0; c < 4; ++c) {
        v[c] = src[lane + 32 * c];
        s += v[c].x * v[c].x + v[c].y * v[c].y + v[c].z * v[c].z + v[c].w * v[c].w;
    }
    #pragma unroll
    for (int off = 16; off > 0; off >>= 1) s += __shfl_xor_sync(0xffffffffu, s, off);

    float scale;
    if (isWO) {
        float inv = 1.f / fmaxf(sqrtf(s), 1e-12f);
        if (lane == 0) {
            d_x2[row] = (s * inv) * inv;
            d_minBits[row] = 0x7F800000u;  // +inf
        }
        scale = inv;
    } else {
        if (lane == 0) d_e2[row] = s;
        scale = 1.f;
    }

    uint2* dst = reinterpret_cast<uint2*>((isWO ? g_WO_bf : g_E_bf) + (size_t)row * DIM);
    #pragma unroll
    for (int c = 0; c < 4; ++c) {
        __nv_bfloat162 p0 = __float22bfloat162_rn(make_float2(v[c].x * scale, v[c].y * scale));
        __nv_bfloat162 p1 = __float22bfloat162_rn(make_float2(v[c].z * scale, v[c].w * scale));
        uint2 u;
        u.x = *reinterpret_cast<uint32_t*>(&p0);
        u.y = *reinterpret_cast<uint32_t*>(&p1);
        dst[lane + 32 * c] = u;
    }
}

// ---------------- kernel 2: fused mma.sync GEMM + d2/min/label epilogue ----------------
// Grid (16, 128). 256 threads = 8 warps (2M x 4N), warp tile 64x32.
// CTA tile 128x128, BK=64, 3-stage cp.async pipeline (ONE __syncthreads per k-iter),
// SW128 swizzle, occupancy 2. (Best measured configuration: 98.3 us, R10/R11.)
#define STAGE_BYTES 32768         // A 16384 + B 16384
#define SMEM_B_IN_STAGE 16384
#define SMEM_RM_OFF (3 * STAGE_BYTES)          // 98304, 128 x 4B
#define SMEM_GEMM_TOTAL (SMEM_RM_OFF + 512)    // 98816

__global__ __launch_bounds__(256, 2)
void gemm_mma(const int* __restrict__ label) {
    extern __shared__ char smem[];
    const uint32_t smem_u32 = smem_to_u32(smem);
    const int tid  = threadIdx.x;
    const int lane = tid & 31;
    const int wid  = tid >> 5;
    const int warpM = wid >> 2;          // 0..1 -> rows warpM*64
    const int warpN = wid & 3;           // 0..3 -> cols warpN*32
    const int rowBase = blockIdx.y * 128;
    const int colBase = blockIdx.x * 128;

    unsigned* rowMinS = reinterpret_cast<unsigned*>(smem + SMEM_RM_OFF);
    if (tid < 128) rowMinS[tid] = 0x7F800000u;

    // stage loader: A 128x64 bf16 (1024 16B chunks) + B 128x64 (1024), 4+4/thread
    auto loadTile = [&](int kt, int s) {
        uint32_t sbase = smem_u32 + s * STAGE_BYTES;
        #pragma unroll
        for (int i = 0; i < 4; ++i) {
            int q = tid + 256 * i;           // 0..1023
            int row = q >> 3, kc = q & 7;
            const void* srcA = g_WO_bf + (size_t)(rowBase + row) * DIM + kt * 64 + kc * 8;
            CP_ASYNC_16(sbase + SW128(row * 128 + kc * 16), srcA);
            const void* srcB = g_E_bf + (size_t)(colBase + row) * DIM + kt * 64 + kc * 8;
            CP_ASYNC_16(sbase + SMEM_B_IN_STAGE + SW128(row * 128 + kc * 16), srcB);
        }
        CP_ASYNC_COMMIT();
    };

    float acc[4][4][4];
    #pragma unroll
    for (int mt = 0; mt < 4; ++mt)
        #pragma unroll
        for (int nt = 0; nt < 4; ++nt)
            #pragma unroll
            for (int e = 0; e < 4; ++e) acc[mt][nt][e] = 0.f;

    const int aRowOff = (warpM * 64 + (lane & 7) + ((lane >> 3) & 1) * 8) * 128 + (lane >> 4) * 16;
    const int bRowOff = (warpN * 32 + (lane & 7) + (lane >> 4) * 8) * 128 + ((lane >> 3) & 1) * 16;

    loadTile(0, 0);
    loadTile(1, 1);

    #pragma unroll 1
    for (int kt = 0; kt < 8; ++kt) {
        if (kt < 6) CP_ASYNC_WAIT1();   // stage kt resident (kt+1 may be in flight)
        else        CP_ASYNC_WAIT0();
        __syncthreads();                // all reads of stage kt-1 done
        if (kt + 2 < 8) loadTile(kt + 2, (kt + 2) % 3);  // fills slot (kt-1)%3 — safe

        const uint32_t sA = smem_u32 + (kt % 3) * STAGE_BYTES;
        const uint32_t sB = sA + SMEM_B_IN_STAGE;
        #pragma unroll
        for (int ks = 0; ks < 4; ++ks) {
            uint32_t aF[4][4], bF[4][2];
            #pragma unroll
            for (int mt = 0; mt < 4; ++mt)
                ldsm_x4(aF[mt], sA + SW128(aRowOff + mt * 2048 + ks * 32));
            #pragma unroll
            for (int pr = 0; pr < 2; ++pr) {
                uint32_t t[4];
                ldsm_x4(t, sB + SW128(bRowOff + pr * 2048 + ks * 32));
                bF[2 * pr + 0][0] = t[0]; bF[2 * pr + 0][1] = t[1];
                bF[2 * pr + 1][0] = t[2]; bF[2 * pr + 1][1] = t[3];
            }
            #pragma unroll
            for (int mt = 0; mt < 4; ++mt)
                #pragma unroll
                for (int nt = 0; nt < 4; ++nt)
                    mma_16816(acc[mt][nt], aF[mt], bF[nt]);
        }
    }

    // epilogue in d^2 space: d2 = x2 + e2 - 2*dot; exclude label col from min
    #pragma unroll
    for (int mt = 0; mt < 4; ++mt) {
        #pragma unroll
        for (int half = 0; half < 2; ++half) {
            int rl = warpM * 64 + mt * 16 + (lane >> 2) + half * 8;
            int r  = rowBase + rl;
            float x2v = __ldg(&d_x2[r]);
            int   lab = __ldg(&label[r]);
            float m = __int_as_float(0x7f800000);
            #pragma unroll
            for (int nt = 0; nt < 4; ++nt) {
                int c0 = colBase + warpN * 32 + nt * 8 + 2 * (lane & 3);
                float d20 = fmaf(-2.f, acc[mt][nt][half * 2 + 0], x2v + __ldg(&d_e2[c0]));
                float d21 = fmaf(-2.f, acc[mt][nt][half * 2 + 1], x2v + __ldg(&d_e2[c0 + 1]));
                if (c0 == lab)     d_labelD2[r] = d20;
                else               m = fminf(m, d20);
                if (c0 + 1 == lab) d_labelD2[r] = d21;
                else               m = fminf(m, d21);
            }
            m = fminf(m, __shfl_xor_sync(0xffffffffu, m, 1));
            m = fminf(m, __shfl_xor_sync(0xffffffffu, m, 2));
            if ((lane & 3) == 0) atomicMin(&rowMinS[rl], __float_as_uint(m));
        }
    }
    __syncthreads();
    if (tid < 128)
        atomicMin(&d_minBits[rowBase + tid], rowMinS[tid]);
}

// ---------------- kernel 3: loss reduction, single kernel (last block finishes) ------
__global__ void loss_reduce(float* __restrict__ out) {
    int tid = threadIdx.x;
    int n = blockIdx.x * 256 + tid;
    float ld = sqrtf(fmaxf(d_labelD2[n], 0.f));
    float md = sqrtf(fmaxf(__uint_as_float(d_minBits[n]), 0.f));
    float s = MARGIN + ld - md;
    #pragma unroll
    for (int off = 16; off > 0; off >>= 1) s += __shfl_xor_sync(0xffffffffu, s, off);
    __shared__ float sb[8];
    __shared__ unsigned lastFlag;
    if ((tid & 31) == 0) sb[tid >> 5] = s;
    __syncthreads();
    if (tid == 0) {
        float v = sb[0] + sb[1] + sb[2] + sb[3] + sb[4] + sb[5] + sb[6] + sb[7];
        d_partial[blockIdx.x] = v;
        __threadfence();
        unsigned prev = atomicInc(&d_cnt, 63);   // wraps to 0 after the 64th -> graph-replay safe
        lastFlag = (prev == 63) ? 1u : 0u;
    }
    __syncthreads();
    if (lastFlag) {
        __threadfence();
        if (tid < 32) {
            float v = d_partial[tid] + d_partial[tid + 32];
            #pragma unroll
            for (int off = 16; off > 0; off >>= 1) v += __shfl_xor_sync(0xffffffffu, v, off);
            if (tid == 0) out[0] = v / (float)N_ROWS;
        }
    }
}

// ---------------- launch ----------------
extern "C" void kernel_launch(void* const* d_in, const int* in_sizes, int n_in,
                              void* d_out, int out_size) {
    const float* WO    = (const float*)d_in[0];
    const float* E     = (const float*)d_in[1];
    const int*   label = (const int*)d_in[2];
    float* out = (float*)d_out;

    cudaFuncSetAttribute(gemm_mma, cudaFuncAttributeMaxDynamicSharedMemorySize, SMEM_GEMM_TOTAL);

    prep_all<<<(N_ROWS + N_CLS) / 8, 256>>>(WO, E);   // launch 1 (merged preps)
    dim3 grid(N_CLS / 128, N_ROWS / 128);             // (16, 128)
    gemm_mma<<<grid, 256, SMEM_GEMM_TOTAL>>>(label);  // launch 2
    loss_reduce<<<64, 256>>>(out);                    // launch 3
}